// round 2
// baseline (speedup 1.0000x reference)
#include <cuda_runtime.h>
#include <math.h>

#define BB 32
#define NN 128
#define OBSD 32
#define HD 128
#define MD 128
#define NLAYERS 3
#define ROWS (BB*NN)      // 4096
#define TR 16             // rows per block for the small row-tile kernels

// ---------------- scratch (static device globals; no allocation) -----------
__device__ float g_z[ROWS*HD];       // node state
__device__ float g_A[ROWS*MD];       // z @ w1a + b1   (row-major)
__device__ float g_BpT[BB*MD*NN];    // (z @ w1b) transposed per batch: [b][f][j]
__device__ float g_S[ROWS*MD];       // sum_{j!=i} H2[j,:]

// ---------------- encoder: obs(4096x32) -> H -> H -> H --------------------
__global__ void enc_kernel(const float* __restrict__ obs,
                           const float* __restrict__ w1, const float* __restrict__ b1,
                           const float* __restrict__ w2, const float* __restrict__ b2,
                           const float* __restrict__ w3, const float* __restrict__ b3)
{
    __shared__ float s_in[TR][OBSD];
    __shared__ float s_h[TR][HD];
    __shared__ float s_h2[TR][HD];
    const int c = threadIdx.x;           // 0..127 (output column)
    const int row0 = blockIdx.x * TR;

    for (int idx = c; idx < TR*OBSD; idx += HD)
        s_in[idx / OBSD][idx % OBSD] = obs[row0*OBSD + idx];
    __syncthreads();

    float acc[TR];
#pragma unroll
    for (int r = 0; r < TR; r++) acc[r] = b1[c];
    for (int k = 0; k < OBSD; k++) {
        float wv = w1[k*HD + c];
#pragma unroll
        for (int r = 0; r < TR; r++) acc[r] += s_in[r][k]*wv;
    }
#pragma unroll
    for (int r = 0; r < TR; r++) s_h[r][c] = fmaxf(acc[r], 0.f);
    __syncthreads();

#pragma unroll
    for (int r = 0; r < TR; r++) acc[r] = b2[c];
    for (int k = 0; k < HD; k++) {
        float wv = w2[k*HD + c];
#pragma unroll
        for (int r = 0; r < TR; r++) acc[r] += s_h[r][k]*wv;
    }
#pragma unroll
    for (int r = 0; r < TR; r++) s_h2[r][c] = fmaxf(acc[r], 0.f);
    __syncthreads();

#pragma unroll
    for (int r = 0; r < TR; r++) acc[r] = b3[c];
    for (int k = 0; k < HD; k++) {
        float wv = w3[k*HD + c];
#pragma unroll
        for (int r = 0; r < TR; r++) acc[r] += s_h2[r][k]*wv;
    }
#pragma unroll
    for (int r = 0; r < TR; r++) g_z[(row0+r)*HD + c] = acc[r];
}

// -------- per-node projections for message layer 1 --------
// A   = z @ w1[0:H]   + b1   (row-major)
// BpT = z @ w1[H:2H]          (stored transposed per batch: [b][f][j])
__global__ void pairproj_kernel(const float* __restrict__ w1,
                                const float* __restrict__ b1)
{
    __shared__ float s_z[TR][HD];
    const int c = threadIdx.x;
    const int row0 = blockIdx.x * TR;
    for (int r = 0; r < TR; r++)
        s_z[r][c] = g_z[(row0+r)*HD + c];
    __syncthreads();

    float accA[TR], accB[TR];
#pragma unroll
    for (int r = 0; r < TR; r++) { accA[r] = b1[c]; accB[r] = 0.f; }
    for (int k = 0; k < HD; k++) {
        float wa = w1[k*MD + c];
        float wb = w1[(HD + k)*MD + c];
#pragma unroll
        for (int r = 0; r < TR; r++) {
            float zv = s_z[r][k];
            accA[r] += zv*wa;
            accB[r] += zv*wb;
        }
    }
    const int b  = row0 / NN;
    const int j0 = row0 % NN;
#pragma unroll
    for (int r = 0; r < TR; r++) {
        g_A[(row0+r)*MD + c] = accA[r];
        g_BpT[b*(MD*NN) + c*NN + (j0+r)] = accB[r];
    }
}

// -------- hot kernel: one block per (b,i) --------
// Build H1[j,f] = relu(A[i,f] + Bp[j,f] + d_ij * w1d[f])   (f-major in smem)
// GEMM+reduce:   S[i,m] = sum_{j != i} relu( (H1 @ w2)[j,m] + b2[m] )
__global__ void __launch_bounds__(512, 1) pair_kernel(
    const float* __restrict__ pos,
    const float* __restrict__ w1d,
    const float* __restrict__ w2,
    const float* __restrict__ b2)
{
    extern __shared__ float smem[];
    float* H1s  = smem;            // 16384 floats : [f][j]
    float* W2s  = smem + 16384;    // 16384 floats : [k][m]
    float* dsh  = smem + 32768;    // 128
    float* sred = smem + 32896;    // 16*128

    const int tid   = threadIdx.x;
    const int bi    = blockIdx.x;      // b*128 + i
    const int b     = bi >> 7;
    const int inode = bi & 127;

    // stage w2 into smem (reused 128x per block)
    {
        const float4* src = (const float4*)w2;
        float4* dst = (float4*)W2s;
        for (int idx = tid; idx < 4096; idx += 512) dst[idx] = src[idx];
    }
    // pairwise distances to node i
    if (tid < NN) {
        const float2 pi = ((const float2*)pos)[b*NN + inode];
        const float2 pj = ((const float2*)pos)[b*NN + tid];
        float dx = pi.x - pj.x, dy = pi.y - pj.y;
        dsh[tid] = sqrtf(dx*dx + dy*dy);
    }
    __syncthreads();

    // build H1 (f-major, coalesced reads of BpT, broadcast A/w1d)
    {
        const float* Arow = g_A + bi*MD;
        const float* Bp   = g_BpT + b*(MD*NN);
#pragma unroll
        for (int it = 0; it < 32; it++) {
            int idx = it*512 + tid;       // idx = f*128 + j
            int f = idx >> 7;
            int j = idx & 127;
            float v = Arow[f] + Bp[idx] + dsh[j]*w1d[f];
            H1s[idx] = fmaxf(v, 0.f);
        }
    }
    __syncthreads();

    // 128x128x128 GEMM, thread tile 8(j) x 4(m), H1 reads are warp-broadcast
    const int tidm = tid & 31;
    const int tidj = tid >> 5;
    const int m0 = tidm*4;
    const int j0 = tidj*8;
    float acc[8][4];
#pragma unroll
    for (int jj = 0; jj < 8; jj++)
#pragma unroll
        for (int mm = 0; mm < 4; mm++) acc[jj][mm] = 0.f;

#pragma unroll 8
    for (int k = 0; k < 128; k++) {
        float4 wv = *(const float4*)&W2s[k*128 + m0];
        float4 ha = *(const float4*)&H1s[k*128 + j0];
        float4 hb = *(const float4*)&H1s[k*128 + j0 + 4];
        float hj[8] = {ha.x, ha.y, ha.z, ha.w, hb.x, hb.y, hb.z, hb.w};
#pragma unroll
        for (int jj = 0; jj < 8; jj++) {
            acc[jj][0] += hj[jj]*wv.x;
            acc[jj][1] += hj[jj]*wv.y;
            acc[jj][2] += hj[jj]*wv.z;
            acc[jj][3] += hj[jj]*wv.w;
        }
    }

    // epilogue: +b2, relu, reduce over j (skip j == i)
    float4 b2v = *(const float4*)&b2[m0];
    float bias[4] = {b2v.x, b2v.y, b2v.z, b2v.w};
#pragma unroll
    for (int mm = 0; mm < 4; mm++) {
        float s = 0.f;
#pragma unroll
        for (int jj = 0; jj < 8; jj++) {
            float v = fmaxf(acc[jj][mm] + bias[mm], 0.f);
            s += (j0 + jj != inode) ? v : 0.f;
        }
        sred[tidj*128 + m0 + mm] = s;
    }
    __syncthreads();
    if (tid < 128) {
        float s = 0.f;
#pragma unroll
        for (int t = 0; t < 16; t++) s += sred[t*128 + tid];
        g_S[bi*MD + tid] = s;
    }
}

// -------- msg = S @ w3 + 127*b3 ; then update MLP (fused) --------
__global__ void upd_kernel(const float* __restrict__ w3, const float* __restrict__ b3,
                           const float* __restrict__ uw1, const float* __restrict__ ub1,
                           const float* __restrict__ uw2, const float* __restrict__ ub2,
                           const float* __restrict__ uw3, const float* __restrict__ ub3,
                           float* __restrict__ out, int write_out)
{
    __shared__ float sS[TR][MD];
    __shared__ float sZ[TR][HD];
    __shared__ float sMsg[TR][MD];
    __shared__ float sT[TR][HD];
    const int c = threadIdx.x;
    const int row0 = blockIdx.x * TR;

    for (int r = 0; r < TR; r++) {
        sS[r][c] = g_S[(row0+r)*MD + c];
        sZ[r][c] = g_z[(row0+r)*HD + c];
    }
    __syncthreads();

    float acc[TR];
    // msg = S @ w3 + 127*b3
#pragma unroll
    for (int r = 0; r < TR; r++) acc[r] = 127.0f * b3[c];
    for (int k = 0; k < MD; k++) {
        float wv = w3[k*MD + c];
#pragma unroll
        for (int r = 0; r < TR; r++) acc[r] += sS[r][k]*wv;
    }
#pragma unroll
    for (int r = 0; r < TR; r++) sMsg[r][c] = acc[r];
    __syncthreads();

    // u1 = relu(z@uw1[0:H] + msg@uw1[H:H+M] + ub1)
#pragma unroll
    for (int r = 0; r < TR; r++) acc[r] = ub1[c];
    for (int k = 0; k < HD; k++) {
        float wv = uw1[k*HD + c];
#pragma unroll
        for (int r = 0; r < TR; r++) acc[r] += sZ[r][k]*wv;
    }
    for (int k = 0; k < MD; k++) {
        float wv = uw1[(HD + k)*HD + c];
#pragma unroll
        for (int r = 0; r < TR; r++) acc[r] += sMsg[r][k]*wv;
    }
#pragma unroll
    for (int r = 0; r < TR; r++) sT[r][c] = fmaxf(acc[r], 0.f);
    __syncthreads();

    // u2 = relu(u1 @ uw2 + ub2)  (write into sMsg, free after previous sync)
#pragma unroll
    for (int r = 0; r < TR; r++) acc[r] = ub2[c];
    for (int k = 0; k < HD; k++) {
        float wv = uw2[k*HD + c];
#pragma unroll
        for (int r = 0; r < TR; r++) acc[r] += sT[r][k]*wv;
    }
#pragma unroll
    for (int r = 0; r < TR; r++) sMsg[r][c] = fmaxf(acc[r], 0.f);
    __syncthreads();

    // z_new = u2 @ uw3 + ub3
#pragma unroll
    for (int r = 0; r < TR; r++) acc[r] = ub3[c];
    for (int k = 0; k < HD; k++) {
        float wv = uw3[k*HD + c];
#pragma unroll
        for (int r = 0; r < TR; r++) acc[r] += sMsg[r][k]*wv;
    }
    if (write_out) {
#pragma unroll
        for (int r = 0; r < TR; r++) out[(row0+r)*HD + c] = acc[r];
    } else {
#pragma unroll
        for (int r = 0; r < TR; r++) g_z[(row0+r)*HD + c] = acc[r];
    }
}

extern "C" void kernel_launch(void* const* d_in, const int* in_sizes, int n_in,
                              void* d_out, int out_size)
{
    const float* obs    = (const float*)d_in[0];
    const float* pos    = (const float*)d_in[1];
    const float* enc_w1 = (const float*)d_in[2];
    const float* enc_b1 = (const float*)d_in[3];
    const float* enc_w2 = (const float*)d_in[4];
    const float* enc_b2 = (const float*)d_in[5];
    const float* enc_w3 = (const float*)d_in[6];
    const float* enc_b3 = (const float*)d_in[7];
    const float* msg_w1 = (const float*)d_in[8];
    const float* msg_b1 = (const float*)d_in[9];
    const float* msg_w2 = (const float*)d_in[10];
    const float* msg_b2 = (const float*)d_in[11];
    const float* msg_w3 = (const float*)d_in[12];
    const float* msg_b3 = (const float*)d_in[13];
    const float* upd_w1 = (const float*)d_in[14];
    const float* upd_b1 = (const float*)d_in[15];
    const float* upd_w2 = (const float*)d_in[16];
    const float* upd_b2 = (const float*)d_in[17];
    const float* upd_w3 = (const float*)d_in[18];
    const float* upd_b3 = (const float*)d_in[19];
    float* out = (float*)d_out;

    const int smem_pair = (16384 + 16384 + 128 + 16*128) * (int)sizeof(float);
    cudaFuncSetAttribute(pair_kernel, cudaFuncAttributeMaxDynamicSharedMemorySize, smem_pair);

    enc_kernel<<<ROWS/TR, HD>>>(obs, enc_w1, enc_b1, enc_w2, enc_b2, enc_w3, enc_b3);

    for (int l = 0; l < NLAYERS; l++) {
        const float* w1 = msg_w1 + (size_t)l*(2*HD+1)*MD;
        const float* b1 = msg_b1 + (size_t)l*MD;
        const float* w2 = msg_w2 + (size_t)l*MD*MD;
        const float* b2 = msg_b2 + (size_t)l*MD;
        const float* w3 = msg_w3 + (size_t)l*MD*MD;
        const float* b3 = msg_b3 + (size_t)l*MD;
        const float* uw1 = upd_w1 + (size_t)l*(HD+MD)*HD;
        const float* ub1 = upd_b1 + (size_t)l*HD;
        const float* uw2 = upd_w2 + (size_t)l*HD*HD;
        const float* ub2 = upd_b2 + (size_t)l*HD;
        const float* uw3 = upd_w3 + (size_t)l*HD*HD;
        const float* ub3 = upd_b3 + (size_t)l*HD;

        pairproj_kernel<<<ROWS/TR, HD>>>(w1, b1);
        pair_kernel<<<ROWS, 512, smem_pair>>>(pos, w1 + 2*HD*MD, w2, b2);
        upd_kernel<<<ROWS/TR, HD>>>(w3, b3, uw1, ub1, uw2, ub2, uw3, ub3,
                                    out, (l == NLAYERS-1) ? 1 : 0);
    }
}

// round 4
// speedup vs baseline: 2.2702x; 2.2702x over previous
#include <cuda_runtime.h>
#include <cuda_bf16.h>
#include <cstdint>
#include <math.h>

#define BB 32
#define NN 128
#define OBSD 32
#define HD 128
#define MD 128
#define NLAYERS 3
#define ROWS (BB*NN)      // 4096
#define TRE 16            // rows/block: encoder
#define TRU 8             // rows/block: pairproj / upd (occupancy fix)

// ---------------- scratch (static device globals; no allocation) -----------
__device__ float g_z[ROWS*HD];
__device__ float g_A[ROWS*MD];
__device__ float g_BpT[BB*MD*NN];    // [b][f][j]
__device__ float g_S[ROWS*MD];
__device__ __align__(16) __nv_bfloat16 g_Whi[MD*MD];   // w2^T hi  [m][k]
__device__ __align__(16) __nv_bfloat16 g_Wlo[MD*MD];   // w2^T lo  [m][k]

// ---------------- encoder: obs(4096x32) -> H -> H -> H --------------------
__global__ void enc_kernel(const float* __restrict__ obs,
                           const float* __restrict__ w1, const float* __restrict__ b1,
                           const float* __restrict__ w2, const float* __restrict__ b2,
                           const float* __restrict__ w3, const float* __restrict__ b3)
{
    __shared__ float s_in[TRE][OBSD];
    __shared__ float s_h[TRE][HD];
    __shared__ float s_h2[TRE][HD];
    const int c = threadIdx.x;
    const int row0 = blockIdx.x * TRE;

    for (int idx = c; idx < TRE*OBSD; idx += HD)
        s_in[idx / OBSD][idx % OBSD] = obs[row0*OBSD + idx];
    __syncthreads();

    float acc[TRE];
#pragma unroll
    for (int r = 0; r < TRE; r++) acc[r] = b1[c];
    for (int k = 0; k < OBSD; k++) {
        float wv = w1[k*HD + c];
#pragma unroll
        for (int r = 0; r < TRE; r++) acc[r] += s_in[r][k]*wv;
    }
#pragma unroll
    for (int r = 0; r < TRE; r++) s_h[r][c] = fmaxf(acc[r], 0.f);
    __syncthreads();

#pragma unroll
    for (int r = 0; r < TRE; r++) acc[r] = b2[c];
    for (int k = 0; k < HD; k++) {
        float wv = w2[k*HD + c];
#pragma unroll
        for (int r = 0; r < TRE; r++) acc[r] += s_h[r][k]*wv;
    }
#pragma unroll
    for (int r = 0; r < TRE; r++) s_h2[r][c] = fmaxf(acc[r], 0.f);
    __syncthreads();

#pragma unroll
    for (int r = 0; r < TRE; r++) acc[r] = b3[c];
    for (int k = 0; k < HD; k++) {
        float wv = w3[k*HD + c];
#pragma unroll
        for (int r = 0; r < TRE; r++) acc[r] += s_h2[r][k]*wv;
    }
#pragma unroll
    for (int r = 0; r < TRE; r++) g_z[(row0+r)*HD + c] = acc[r];
}

// -------- per-node projections for message layer 1 --------
__global__ void pairproj_kernel(const float* __restrict__ w1,
                                const float* __restrict__ b1)
{
    __shared__ float s_z[TRU][HD];
    const int c = threadIdx.x;
    const int row0 = blockIdx.x * TRU;
    for (int r = 0; r < TRU; r++)
        s_z[r][c] = g_z[(row0+r)*HD + c];
    __syncthreads();

    float accA[TRU], accB[TRU];
#pragma unroll
    for (int r = 0; r < TRU; r++) { accA[r] = b1[c]; accB[r] = 0.f; }
    for (int k = 0; k < HD; k++) {
        float wa = w1[k*MD + c];
        float wb = w1[(HD + k)*MD + c];
#pragma unroll
        for (int r = 0; r < TRU; r++) {
            float zv = s_z[r][k];
            accA[r] += zv*wa;
            accB[r] += zv*wb;
        }
    }
    const int b  = row0 / NN;
    const int j0 = row0 % NN;
#pragma unroll
    for (int r = 0; r < TRU; r++) {
        g_A[(row0+r)*MD + c] = accA[r];
        g_BpT[b*(MD*NN) + c*NN + (j0+r)] = accB[r];
    }
}

// -------- prep: w2 (fp32 [k][m]) -> w2^T hi/lo bf16 [m][k] -----------------
__global__ void prep_w2_kernel(const float* __restrict__ w2)
{
    int e = blockIdx.x * 128 + threadIdx.x;   // 16384 elems
    int m = e >> 7, k = e & 127;
    float v = w2[k*MD + m];
    __nv_bfloat16 hi = __float2bfloat16(v);
    __nv_bfloat16 lo = __float2bfloat16(v - __bfloat162float(hi));
    g_Whi[m*MD + k] = hi;
    g_Wlo[m*MD + k] = lo;
}

// ======================= pair kernel (mma.sync HMMA) ========================
// Per block (b,i):
//   H1[j,k] = relu(A[i,k] + Bp[k,j] + d_ij*w1d[k])  (bf16 in smem, stride 136)
//   D[j,m]  = H1 @ (Whi + Wlo)^T  via mma.sync m16n8k16, fp32 accum (2 passes)
//   S[i,m]  = sum_{j != i} relu(D[j,m] + b2[m])
#define PADH 136                 // halves per row (272 bytes) -> conflict-free frags
#define TILE_BYTES (128*PADH*2)  // 34816
#define OFF_H1   0
#define OFF_WHI  TILE_BYTES
#define OFF_WLO  (2*TILE_BYTES)
#define OFF_AUX  (3*TILE_BYTES)
#define SMEM_PAIR (OFF_AUX + 4096)

__device__ __forceinline__ void mma_bf16(float c[4], uint32_t a0, uint32_t a1,
                                         uint32_t a2, uint32_t a3,
                                         uint32_t b0, uint32_t b1) {
    asm volatile(
        "mma.sync.aligned.m16n8k16.row.col.f32.bf16.bf16.f32 "
        "{%0,%1,%2,%3}, {%4,%5,%6,%7}, {%8,%9}, {%0,%1,%2,%3};"
        : "+f"(c[0]), "+f"(c[1]), "+f"(c[2]), "+f"(c[3])
        : "r"(a0), "r"(a1), "r"(a2), "r"(a3), "r"(b0), "r"(b1));
}

__global__ void __launch_bounds__(256, 2) tc_pair_kernel(
    const float* __restrict__ pos,
    const float* __restrict__ w1d,
    const float* __restrict__ b2)
{
    extern __shared__ __align__(16) char s[];
    float* dsh  = (float*)(s + OFF_AUX);          // 128
    float* sA   = (float*)(s + OFF_AUX + 512);    // 128
    float* sW1d = (float*)(s + OFF_AUX + 1024);   // 128
    float* b2s  = (float*)(s + OFF_AUX + 1536);   // 128
    float* red  = (float*)(s + OFF_AUX + 2048);   // 4 x 128

    const int tid  = threadIdx.x;
    const int wid  = tid >> 5;
    const int lane = tid & 31;
    const int g    = lane >> 2;       // group id 0..7
    const int tig  = lane & 3;        // thread in group
    const int wj   = wid & 3;         // j quarter (32 rows)
    const int wm   = wid >> 2;        // m half   (64 cols)
    const int bi    = blockIdx.x;
    const int b     = bi >> 7;
    const int inode = bi & 127;

    // stage W tiles with padding ([m][k], 64 b32/row -> stride 68 b32)
    {
        uint32_t* dhi = (uint32_t*)(s + OFF_WHI);
        uint32_t* dlo = (uint32_t*)(s + OFF_WLO);
        const uint32_t* shi = (const uint32_t*)g_Whi;
        const uint32_t* slo = (const uint32_t*)g_Wlo;
        for (int i = tid; i < 8192; i += 256) {
            int row = i >> 6, col = i & 63;
            dhi[row*68 + col] = shi[i];
            dlo[row*68 + col] = slo[i];
        }
    }
    if (tid < 128) {
        const float2 pi = ((const float2*)pos)[b*NN + inode];
        const float2 pj = ((const float2*)pos)[b*NN + tid];
        float dx = pi.x - pj.x, dy = pi.y - pj.y;
        dsh[tid]  = sqrtf(dx*dx + dy*dy);
        sA[tid]   = g_A[bi*MD + tid];
        sW1d[tid] = w1d[tid];
        b2s[tid]  = b2[tid];
    }
    __syncthreads();

    // build H1 (bf16, [j][k] stride PADH halves)
    {
        const float* Bp = g_BpT + b*(MD*NN);
        __nv_bfloat162* H1 = (__nv_bfloat162*)(s + OFF_H1);
        for (int it = tid; it < 8192; it += 256) {
            int fp = it >> 7, j = it & 127;
            int f0 = fp << 1;
            float d = dsh[j];
            float v0 = fmaxf(sA[f0]   + Bp[f0*NN + j]     + d*sW1d[f0],   0.f);
            float v1 = fmaxf(sA[f0+1] + Bp[(f0+1)*NN + j] + d*sW1d[f0+1], 0.f);
            H1[(j*PADH + f0) >> 1] = __floats2bfloat162_rn(v0, v1);
        }
    }
    __syncthreads();

    // warp GEMM: 32j x 64m, K=128, two passes (Whi then Wlo), fp32 accum
    float acc[2][8][4];
#pragma unroll
    for (int jt = 0; jt < 2; jt++)
#pragma unroll
        for (int nt = 0; nt < 8; nt++)
#pragma unroll
            for (int q = 0; q < 4; q++) acc[jt][nt][q] = 0.f;

    const char* H1b = s + OFF_H1;
#pragma unroll
    for (int pass = 0; pass < 2; pass++) {
        const char* Wb = s + (pass ? OFF_WLO : OFF_WHI);
#pragma unroll
        for (int kk = 0; kk < 8; kk++) {
            uint32_t a[2][4];
#pragma unroll
            for (int jt = 0; jt < 2; jt++) {
                const char* ab = H1b + (wj*32 + jt*16 + g)*(PADH*2) + kk*32 + tig*4;
                a[jt][0] = *(const uint32_t*)(ab);
                a[jt][1] = *(const uint32_t*)(ab + 8*(PADH*2));
                a[jt][2] = *(const uint32_t*)(ab + 16);
                a[jt][3] = *(const uint32_t*)(ab + 8*(PADH*2) + 16);
            }
#pragma unroll
            for (int nt = 0; nt < 8; nt++) {
                const char* bb = Wb + (wm*64 + nt*8 + g)*(PADH*2) + kk*32 + tig*4;
                uint32_t b0 = *(const uint32_t*)(bb);
                uint32_t b1 = *(const uint32_t*)(bb + 16);
                mma_bf16(acc[0][nt], a[0][0], a[0][1], a[0][2], a[0][3], b0, b1);
                mma_bf16(acc[1][nt], a[1][0], a[1][1], a[1][2], a[1][3], b0, b1);
            }
        }
    }

    // epilogue: +b2, relu, zero diag row, reduce over 32 j rows of this warp
#pragma unroll
    for (int nt = 0; nt < 8; nt++) {
        const int col0 = wm*64 + nt*8 + 2*tig;
        const float bias0 = b2s[col0], bias1 = b2s[col0 + 1];
        float s0 = 0.f, s1 = 0.f;
#pragma unroll
        for (int jt = 0; jt < 2; jt++) {
            int r0 = wj*32 + jt*16 + g;
            int r1 = r0 + 8;
            float v0 = fmaxf(acc[jt][nt][0] + bias0, 0.f);
            float v1 = fmaxf(acc[jt][nt][1] + bias1, 0.f);
            float v2 = fmaxf(acc[jt][nt][2] + bias0, 0.f);
            float v3 = fmaxf(acc[jt][nt][3] + bias1, 0.f);
            if (r0 == inode) { v0 = 0.f; v1 = 0.f; }
            if (r1 == inode) { v2 = 0.f; v3 = 0.f; }
            s0 += v0 + v2;
            s1 += v1 + v3;
        }
#pragma unroll
        for (int off = 4; off < 32; off <<= 1) {
            s0 += __shfl_xor_sync(0xffffffffu, s0, off);
            s1 += __shfl_xor_sync(0xffffffffu, s1, off);
        }
        if (g == 0) {
            red[wj*128 + col0]     = s0;
            red[wj*128 + col0 + 1] = s1;
        }
    }
    __syncthreads();

    if (tid < 128)
        g_S[bi*MD + tid] = red[tid] + red[128 + tid] + red[256 + tid] + red[384 + tid];
}

// -------- msg = S @ w3 + 127*b3 ; then update MLP (fused) --------
__global__ void upd_kernel(const float* __restrict__ w3, const float* __restrict__ b3,
                           const float* __restrict__ uw1, const float* __restrict__ ub1,
                           const float* __restrict__ uw2, const float* __restrict__ ub2,
                           const float* __restrict__ uw3, const float* __restrict__ ub3,
                           float* __restrict__ out, int write_out)
{
    __shared__ float sS[TRU][MD];
    __shared__ float sZ[TRU][HD];
    __shared__ float sMsg[TRU][MD];
    __shared__ float sT[TRU][HD];
    const int c = threadIdx.x;
    const int row0 = blockIdx.x * TRU;

    for (int r = 0; r < TRU; r++) {
        sS[r][c] = g_S[(row0+r)*MD + c];
        sZ[r][c] = g_z[(row0+r)*HD + c];
    }
    __syncthreads();

    float acc[TRU];
#pragma unroll
    for (int r = 0; r < TRU; r++) acc[r] = 127.0f * b3[c];
    for (int k = 0; k < MD; k++) {
        float wv = w3[k*MD + c];
#pragma unroll
        for (int r = 0; r < TRU; r++) acc[r] += sS[r][k]*wv;
    }
#pragma unroll
    for (int r = 0; r < TRU; r++) sMsg[r][c] = acc[r];
    __syncthreads();

#pragma unroll
    for (int r = 0; r < TRU; r++) acc[r] = ub1[c];
    for (int k = 0; k < HD; k++) {
        float wv = uw1[k*HD + c];
#pragma unroll
        for (int r = 0; r < TRU; r++) acc[r] += sZ[r][k]*wv;
    }
    for (int k = 0; k < MD; k++) {
        float wv = uw1[(HD + k)*HD + c];
#pragma unroll
        for (int r = 0; r < TRU; r++) acc[r] += sMsg[r][k]*wv;
    }
#pragma unroll
    for (int r = 0; r < TRU; r++) sT[r][c] = fmaxf(acc[r], 0.f);
    __syncthreads();

#pragma unroll
    for (int r = 0; r < TRU; r++) acc[r] = ub2[c];
    for (int k = 0; k < HD; k++) {
        float wv = uw2[k*HD + c];
#pragma unroll
        for (int r = 0; r < TRU; r++) acc[r] += sT[r][k]*wv;
    }
#pragma unroll
    for (int r = 0; r < TRU; r++) sMsg[r][c] = fmaxf(acc[r], 0.f);
    __syncthreads();

#pragma unroll
    for (int r = 0; r < TRU; r++) acc[r] = ub3[c];
    for (int k = 0; k < HD; k++) {
        float wv = uw3[k*HD + c];
#pragma unroll
        for (int r = 0; r < TRU; r++) acc[r] += sMsg[r][k]*wv;
    }
    if (write_out) {
#pragma unroll
        for (int r = 0; r < TRU; r++) out[(row0+r)*HD + c] = acc[r];
    } else {
#pragma unroll
        for (int r = 0; r < TRU; r++) g_z[(row0+r)*HD + c] = acc[r];
    }
}

extern "C" void kernel_launch(void* const* d_in, const int* in_sizes, int n_in,
                              void* d_out, int out_size)
{
    const float* obs    = (const float*)d_in[0];
    const float* pos    = (const float*)d_in[1];
    const float* enc_w1 = (const float*)d_in[2];
    const float* enc_b1 = (const float*)d_in[3];
    const float* enc_w2 = (const float*)d_in[4];
    const float* enc_b2 = (const float*)d_in[5];
    const float* enc_w3 = (const float*)d_in[6];
    const float* enc_b3 = (const float*)d_in[7];
    const float* msg_w1 = (const float*)d_in[8];
    const float* msg_b1 = (const float*)d_in[9];
    const float* msg_w2 = (const float*)d_in[10];
    const float* msg_b2 = (const float*)d_in[11];
    const float* msg_w3 = (const float*)d_in[12];
    const float* msg_b3 = (const float*)d_in[13];
    const float* upd_w1 = (const float*)d_in[14];
    const float* upd_b1 = (const float*)d_in[15];
    const float* upd_w2 = (const float*)d_in[16];
    const float* upd_b2 = (const float*)d_in[17];
    const float* upd_w3 = (const float*)d_in[18];
    const float* upd_b3 = (const float*)d_in[19];
    float* out = (float*)d_out;

    cudaFuncSetAttribute(tc_pair_kernel,
                         cudaFuncAttributeMaxDynamicSharedMemorySize, SMEM_PAIR);

    enc_kernel<<<ROWS/TRE, HD>>>(obs, enc_w1, enc_b1, enc_w2, enc_b2, enc_w3, enc_b3);

    for (int l = 0; l < NLAYERS; l++) {
        const float* w1 = msg_w1 + (size_t)l*(2*HD+1)*MD;
        const float* b1 = msg_b1 + (size_t)l*MD;
        const float* w2 = msg_w2 + (size_t)l*MD*MD;
        const float* b2 = msg_b2 + (size_t)l*MD;
        const float* w3 = msg_w3 + (size_t)l*MD*MD;
        const float* b3 = msg_b3 + (size_t)l*MD;
        const float* uw1 = upd_w1 + (size_t)l*(HD+MD)*HD;
        const float* ub1 = upd_b1 + (size_t)l*HD;
        const float* uw2 = upd_w2 + (size_t)l*HD*HD;
        const float* ub2 = upd_b2 + (size_t)l*HD;
        const float* uw3 = upd_w3 + (size_t)l*HD*HD;
        const float* ub3 = upd_b3 + (size_t)l*HD;

        prep_w2_kernel<<<128, 128>>>(w2);
        pairproj_kernel<<<ROWS/TRU, HD>>>(w1, b1);
        tc_pair_kernel<<<ROWS, 256, SMEM_PAIR>>>(pos, w1 + 2*HD*MD, b2);
        upd_kernel<<<ROWS/TRU, HD>>>(w3, b3, uw1, ub1, uw2, ub2, uw3, ub3,
                                     out, (l == NLAYERS-1) ? 1 : 0);
    }
}

// round 5
// speedup vs baseline: 2.3724x; 1.0450x over previous
#include <cuda_runtime.h>
#include <cuda_bf16.h>
#include <cstdint>
#include <math.h>

#define BB 32
#define NN 128
#define OBSD 32
#define HD 128
#define MD 128
#define NLAYERS 3
#define ROWS (BB*NN)      // 4096
#define TRE 16            // rows/block: encoder
#define TRU 8             // rows/block: pairproj / upd

// ---------------- scratch (static device globals; no allocation) -----------
__device__ float g_z[ROWS*HD];
__device__ float g_A[ROWS*MD];
__device__ float g_BpT[BB*MD*NN];    // [b][f][j]
__device__ float g_S[ROWS*MD];
__device__ __align__(16) __nv_bfloat16 g_Whi[MD*MD];   // w2^T hi  [m][k]
__device__ __align__(16) __nv_bfloat16 g_Wlo[MD*MD];   // w2^T lo  [m][k]

__device__ __forceinline__ uint32_t smem_u32(const void* p) {
    uint32_t a;
    asm("{ .reg .u64 t; cvta.to.shared.u64 t, %1; cvt.u32.u64 %0, t; }" : "=r"(a) : "l"(p));
    return a;
}

// ---------------- encoder: obs(4096x32) -> H -> H -> H --------------------
__global__ void enc_kernel(const float* __restrict__ obs,
                           const float* __restrict__ w1, const float* __restrict__ b1,
                           const float* __restrict__ w2, const float* __restrict__ b2,
                           const float* __restrict__ w3, const float* __restrict__ b3)
{
    __shared__ float s_in[TRE][OBSD];
    __shared__ float s_h[TRE][HD];
    __shared__ float s_h2[TRE][HD];
    const int c = threadIdx.x;
    const int row0 = blockIdx.x * TRE;

    for (int idx = c; idx < TRE*OBSD; idx += HD)
        s_in[idx / OBSD][idx % OBSD] = obs[row0*OBSD + idx];
    __syncthreads();

    float acc[TRE];
#pragma unroll
    for (int r = 0; r < TRE; r++) acc[r] = b1[c];
    for (int k = 0; k < OBSD; k++) {
        float wv = w1[k*HD + c];
#pragma unroll
        for (int r = 0; r < TRE; r++) acc[r] += s_in[r][k]*wv;
    }
#pragma unroll
    for (int r = 0; r < TRE; r++) s_h[r][c] = fmaxf(acc[r], 0.f);
    __syncthreads();

#pragma unroll
    for (int r = 0; r < TRE; r++) acc[r] = b2[c];
    for (int k = 0; k < HD; k++) {
        float wv = w2[k*HD + c];
#pragma unroll
        for (int r = 0; r < TRE; r++) acc[r] += s_h[r][k]*wv;
    }
#pragma unroll
    for (int r = 0; r < TRE; r++) s_h2[r][c] = fmaxf(acc[r], 0.f);
    __syncthreads();

#pragma unroll
    for (int r = 0; r < TRE; r++) acc[r] = b3[c];
    for (int k = 0; k < HD; k++) {
        float wv = w3[k*HD + c];
#pragma unroll
        for (int r = 0; r < TRE; r++) acc[r] += s_h2[r][k]*wv;
    }
#pragma unroll
    for (int r = 0; r < TRE; r++) g_z[(row0+r)*HD + c] = acc[r];
}

// -------- per-node projections, split-k over 2 thread halves --------
__global__ void __launch_bounds__(256) pairproj_kernel(const float* __restrict__ w1,
                                                       const float* __restrict__ b1)
{
    __shared__ float s_z[TRU][HD];
    __shared__ float sPA[TRU][128];
    __shared__ float sPB[TRU][128];
    const int tid = threadIdx.x;
    const int c  = tid & 127;
    const int kh = tid >> 7;
    const int row0 = blockIdx.x * TRU;

    for (int idx = tid; idx < TRU*HD; idx += 256)
        ((float*)s_z)[idx] = g_z[row0*HD + idx];
    __syncthreads();

    float accA[TRU], accB[TRU];
#pragma unroll
    for (int r = 0; r < TRU; r++) { accA[r] = 0.f; accB[r] = 0.f; }
    const int k0 = kh*64;
#pragma unroll 4
    for (int k = k0; k < k0 + 64; k++) {
        float wa = w1[k*MD + c];
        float wb = w1[(HD + k)*MD + c];
#pragma unroll
        for (int r = 0; r < TRU; r++) {
            float zv = s_z[r][k];
            accA[r] += zv*wa;
            accB[r] += zv*wb;
        }
    }
    if (kh == 1) {
#pragma unroll
        for (int r = 0; r < TRU; r++) { sPA[r][c] = accA[r]; sPB[r][c] = accB[r]; }
    }
    __syncthreads();
    if (kh == 0) {
        const int b  = row0 / NN;
        const int j0 = row0 % NN;
        float bias = b1[c];
#pragma unroll
        for (int r = 0; r < TRU; r++) {
            g_A[(row0+r)*MD + c] = accA[r] + sPA[r][c] + bias;
            g_BpT[b*(MD*NN) + c*NN + (j0+r)] = accB[r] + sPB[r][c];
        }
    }
}

// -------- prep: w2 (fp32 [k][m]) -> w2^T hi/lo bf16 [m][k] -----------------
__global__ void prep_w2_kernel(const float* __restrict__ w2)
{
    int e = blockIdx.x * 128 + threadIdx.x;   // 16384 elems
    int m = e >> 7, k = e & 127;
    float v = w2[k*MD + m];
    __nv_bfloat16 hi = __float2bfloat16(v);
    __nv_bfloat16 lo = __float2bfloat16(v - __bfloat162float(hi));
    g_Whi[m*MD + k] = hi;
    g_Wlo[m*MD + k] = lo;
}

// ======================= pair kernel (mma.sync + ldmatrix) ==================
#define PADH 136                 // halves per row (272 B) -> conflict-free LDSM
#define ROWB (PADH*2)            // 272
#define TILE_BYTES (128*ROWB)    // 34816
#define OFF_H1   0
#define OFF_WHI  TILE_BYTES
#define OFF_WLO  (2*TILE_BYTES)
#define OFF_AUX  (3*TILE_BYTES)
#define SMEM_PAIR (OFF_AUX + 4096)

__device__ __forceinline__ void mma_bf16(float c[4], uint32_t a0, uint32_t a1,
                                         uint32_t a2, uint32_t a3,
                                         uint32_t b0, uint32_t b1) {
    asm volatile(
        "mma.sync.aligned.m16n8k16.row.col.f32.bf16.bf16.f32 "
        "{%0,%1,%2,%3}, {%4,%5,%6,%7}, {%8,%9}, {%0,%1,%2,%3};"
        : "+f"(c[0]), "+f"(c[1]), "+f"(c[2]), "+f"(c[3])
        : "r"(a0), "r"(a1), "r"(a2), "r"(a3), "r"(b0), "r"(b1));
}
#define LDSM_X4(r0, r1, r2, r3, addr) \
    asm volatile("ldmatrix.sync.aligned.m8n8.x4.shared.b16 {%0,%1,%2,%3}, [%4];" \
        : "=r"(r0), "=r"(r1), "=r"(r2), "=r"(r3) : "r"(addr))

__global__ void __launch_bounds__(256, 2) tc_pair_kernel(
    const float* __restrict__ pos,
    const float* __restrict__ w1d,
    const float* __restrict__ b2)
{
    extern __shared__ __align__(16) char s[];
    float* dsh  = (float*)(s + OFF_AUX);          // 128
    float* sA   = (float*)(s + OFF_AUX + 512);    // 128
    float* sW1d = (float*)(s + OFF_AUX + 1024);   // 128
    float* b2s  = (float*)(s + OFF_AUX + 1536);   // 128
    float* red  = (float*)(s + OFF_AUX + 2048);   // 4 x 128

    const int tid  = threadIdx.x;
    const int wid  = tid >> 5;
    const int lane = tid & 31;
    const int g    = lane >> 2;       // group id 0..7
    const int tig  = lane & 3;        // thread in group
    const int wj   = wid & 3;         // j quarter (32 rows)
    const int wm   = wid >> 2;        // m half   (64 cols)
    const int bi    = blockIdx.x;
    const int b     = bi >> 7;
    const int inode = bi & 127;

    // stage W tiles with padded stride (float4: 17 f4 per 68-u32 row)
    {
        float4* dhi = (float4*)(s + OFF_WHI);
        float4* dlo = (float4*)(s + OFF_WLO);
        const float4* shi = (const float4*)g_Whi;
        const float4* slo = (const float4*)g_Wlo;
        for (int i = tid; i < 2048; i += 256) {
            int row = i >> 4, c4 = i & 15;
            dhi[row*17 + c4] = shi[i];
            dlo[row*17 + c4] = slo[i];
        }
    }
    if (tid < 128) {
        const float2 pi = ((const float2*)pos)[b*NN + inode];
        const float2 pj = ((const float2*)pos)[b*NN + tid];
        float dx = pi.x - pj.x, dy = pi.y - pj.y;
        dsh[tid]  = sqrtf(dx*dx + dy*dy);
        sA[tid]   = g_A[bi*MD + tid];
        sW1d[tid] = w1d[tid];
        b2s[tid]  = b2[tid];
    }
    __syncthreads();

    // build H1 (bf16, [j][k] stride 272 B)
    {
        const float* Bp = g_BpT + b*(MD*NN);
        __nv_bfloat162* H1 = (__nv_bfloat162*)(s + OFF_H1);
        for (int it = tid; it < 8192; it += 256) {
            int fp = it >> 7, j = it & 127;
            int f0 = fp << 1;
            float d = dsh[j];
            float v0 = fmaxf(sA[f0]   + Bp[f0*NN + j]     + d*sW1d[f0],   0.f);
            float v1 = fmaxf(sA[f0+1] + Bp[(f0+1)*NN + j] + d*sW1d[f0+1], 0.f);
            H1[(j*PADH + f0) >> 1] = __floats2bfloat162_rn(v0, v1);
        }
    }
    __syncthreads();

    // ---- ldmatrix bases ----
    // A x4: lanes 0-15 -> rows (lane%16), lanes 16-31 same rows at +16 B (k+8)
    const uint32_t sbase = smem_u32(s);
    uint32_t aAddr[2];
#pragma unroll
    for (int jt = 0; jt < 2; jt++)
        aAddr[jt] = sbase + OFF_H1 + (uint32_t)(wj*32 + jt*16 + (lane & 15))*ROWB
                  + (uint32_t)(lane >> 4)*16;
    // B x4: t=lane>>3: n = wm*64 + (t>>1)*8 + (lane&7), kbyte = (t&1)*16
    const int bt = lane >> 3;
    const uint32_t brow = (uint32_t)(wm*64 + (bt >> 1)*8 + (lane & 7))*ROWB
                        + (uint32_t)(bt & 1)*16;
    const uint32_t bHi = sbase + OFF_WHI + brow;
    const uint32_t bLo = sbase + OFF_WLO + brow;

    float acc[2][8][4];
#pragma unroll
    for (int jt = 0; jt < 2; jt++)
#pragma unroll
        for (int nt = 0; nt < 8; nt++)
#pragma unroll
            for (int q = 0; q < 4; q++) acc[jt][nt][q] = 0.f;

#pragma unroll
    for (int kk = 0; kk < 8; kk++) {
        uint32_t a[2][4];
        LDSM_X4(a[0][0], a[0][1], a[0][2], a[0][3], aAddr[0] + kk*32);
        LDSM_X4(a[1][0], a[1][1], a[1][2], a[1][3], aAddr[1] + kk*32);
#pragma unroll
        for (int pass = 0; pass < 2; pass++) {
            const uint32_t bb = (pass ? bLo : bHi) + kk*32;
#pragma unroll
            for (int p = 0; p < 4; p++) {
                uint32_t w0, w1r, w2r, w3r;
                LDSM_X4(w0, w1r, w2r, w3r, bb + p*(16*ROWB));
                mma_bf16(acc[0][2*p],   a[0][0], a[0][1], a[0][2], a[0][3], w0,  w1r);
                mma_bf16(acc[1][2*p],   a[1][0], a[1][1], a[1][2], a[1][3], w0,  w1r);
                mma_bf16(acc[0][2*p+1], a[0][0], a[0][1], a[0][2], a[0][3], w2r, w3r);
                mma_bf16(acc[1][2*p+1], a[1][0], a[1][1], a[1][2], a[1][3], w2r, w3r);
            }
        }
    }

    // epilogue: +b2, relu, zero diag row, reduce over this warp's 32 j rows
#pragma unroll
    for (int nt = 0; nt < 8; nt++) {
        const int col0 = wm*64 + nt*8 + 2*tig;
        const float bias0 = b2s[col0], bias1 = b2s[col0 + 1];
        float s0 = 0.f, s1 = 0.f;
#pragma unroll
        for (int jt = 0; jt < 2; jt++) {
            int r0 = wj*32 + jt*16 + g;
            int r1 = r0 + 8;
            float v0 = fmaxf(acc[jt][nt][0] + bias0, 0.f);
            float v1 = fmaxf(acc[jt][nt][1] + bias1, 0.f);
            float v2 = fmaxf(acc[jt][nt][2] + bias0, 0.f);
            float v3 = fmaxf(acc[jt][nt][3] + bias1, 0.f);
            if (r0 == inode) { v0 = 0.f; v1 = 0.f; }
            if (r1 == inode) { v2 = 0.f; v3 = 0.f; }
            s0 += v0 + v2;
            s1 += v1 + v3;
        }
#pragma unroll
        for (int off = 4; off < 32; off <<= 1) {
            s0 += __shfl_xor_sync(0xffffffffu, s0, off);
            s1 += __shfl_xor_sync(0xffffffffu, s1, off);
        }
        if (g == 0) {
            red[wj*128 + col0]     = s0;
            red[wj*128 + col0 + 1] = s1;
        }
    }
    __syncthreads();

    if (tid < 128)
        g_S[bi*MD + tid] = red[tid] + red[128 + tid] + red[256 + tid] + red[384 + tid];
}

// -------- update MLP, split-k over 2 thread halves --------
__global__ void __launch_bounds__(256) upd_kernel(
        const float* __restrict__ w3, const float* __restrict__ b3,
        const float* __restrict__ uw1, const float* __restrict__ ub1,
        const float* __restrict__ uw2, const float* __restrict__ ub2,
        const float* __restrict__ uw3, const float* __restrict__ ub3,
        float* __restrict__ out, int write_out)
{
    __shared__ float sS[TRU][MD];     // S, later reused as u2
    __shared__ float sZ[TRU][HD];
    __shared__ float sMsg[TRU][MD];
    __shared__ float sT[TRU][HD];
    __shared__ float sP[TRU][128];    // partial-sum exchange
    const int tid = threadIdx.x;
    const int c  = tid & 127;
    const int kh = tid >> 7;
    const int row0 = blockIdx.x * TRU;

    for (int idx = tid; idx < TRU*MD; idx += 256) {
        ((float*)sS)[idx] = g_S[row0*MD + idx];
        ((float*)sZ)[idx] = g_z[row0*HD + idx];
    }
    __syncthreads();

    float acc[TRU];
    // ---- msg = S @ w3 + 127*b3 ----
#pragma unroll
    for (int r = 0; r < TRU; r++) acc[r] = 0.f;
    {
        const int k0 = kh*64;
#pragma unroll 4
        for (int k = k0; k < k0 + 64; k++) {
            float wv = w3[k*MD + c];
#pragma unroll
            for (int r = 0; r < TRU; r++) acc[r] += sS[r][k]*wv;
        }
    }
    if (kh == 1) { for (int r = 0; r < TRU; r++) sP[r][c] = acc[r]; }
    __syncthreads();
    if (kh == 0) {
        float bias = 127.0f * b3[c];
        for (int r = 0; r < TRU; r++) sMsg[r][c] = acc[r] + sP[r][c] + bias;
    }
    __syncthreads();

    // ---- u1 = relu(z@uw1[:H] + msg@uw1[H:] + ub1) : kh0->z half, kh1->msg half
#pragma unroll
    for (int r = 0; r < TRU; r++) acc[r] = 0.f;
    if (kh == 0) {
#pragma unroll 4
        for (int k = 0; k < HD; k++) {
            float wv = uw1[k*HD + c];
#pragma unroll
            for (int r = 0; r < TRU; r++) acc[r] += sZ[r][k]*wv;
        }
    } else {
#pragma unroll 4
        for (int k = 0; k < MD; k++) {
            float wv = uw1[(HD + k)*HD + c];
#pragma unroll
            for (int r = 0; r < TRU; r++) acc[r] += sMsg[r][k]*wv;
        }
    }
    if (kh == 1) { for (int r = 0; r < TRU; r++) sP[r][c] = acc[r]; }
    __syncthreads();
    if (kh == 0) {
        float bias = ub1[c];
        for (int r = 0; r < TRU; r++) sT[r][c] = fmaxf(acc[r] + sP[r][c] + bias, 0.f);
    }
    __syncthreads();

    // ---- u2 = relu(u1 @ uw2 + ub2)  (into sS)
#pragma unroll
    for (int r = 0; r < TRU; r++) acc[r] = 0.f;
    {
        const int k0 = kh*64;
#pragma unroll 4
        for (int k = k0; k < k0 + 64; k++) {
            float wv = uw2[k*HD + c];
#pragma unroll
            for (int r = 0; r < TRU; r++) acc[r] += sT[r][k]*wv;
        }
    }
    if (kh == 1) { for (int r = 0; r < TRU; r++) sP[r][c] = acc[r]; }
    __syncthreads();
    if (kh == 0) {
        float bias = ub2[c];
        for (int r = 0; r < TRU; r++) sS[r][c] = fmaxf(acc[r] + sP[r][c] + bias, 0.f);
    }
    __syncthreads();

    // ---- z_new = u2 @ uw3 + ub3
#pragma unroll
    for (int r = 0; r < TRU; r++) acc[r] = 0.f;
    {
        const int k0 = kh*64;
#pragma unroll 4
        for (int k = k0; k < k0 + 64; k++) {
            float wv = uw3[k*HD + c];
#pragma unroll
            for (int r = 0; r < TRU; r++) acc[r] += sS[r][k]*wv;
        }
    }
    if (kh == 1) { for (int r = 0; r < TRU; r++) sP[r][c] = acc[r]; }
    __syncthreads();
    if (kh == 0) {
        float bias = ub3[c];
        if (write_out) {
            for (int r = 0; r < TRU; r++) out[(row0+r)*HD + c] = acc[r] + sP[r][c] + bias;
        } else {
            for (int r = 0; r < TRU; r++) g_z[(row0+r)*HD + c] = acc[r] + sP[r][c] + bias;
        }
    }
}

extern "C" void kernel_launch(void* const* d_in, const int* in_sizes, int n_in,
                              void* d_out, int out_size)
{
    const float* obs    = (const float*)d_in[0];
    const float* pos    = (const float*)d_in[1];
    const float* enc_w1 = (const float*)d_in[2];
    const float* enc_b1 = (const float*)d_in[3];
    const float* enc_w2 = (const float*)d_in[4];
    const float* enc_b2 = (const float*)d_in[5];
    const float* enc_w3 = (const float*)d_in[6];
    const float* enc_b3 = (const float*)d_in[7];
    const float* msg_w1 = (const float*)d_in[8];
    const float* msg_b1 = (const float*)d_in[9];
    const float* msg_w2 = (const float*)d_in[10];
    const float* msg_b2 = (const float*)d_in[11];
    const float* msg_w3 = (const float*)d_in[12];
    const float* msg_b3 = (const float*)d_in[13];
    const float* upd_w1 = (const float*)d_in[14];
    const float* upd_b1 = (const float*)d_in[15];
    const float* upd_w2 = (const float*)d_in[16];
    const float* upd_b2 = (const float*)d_in[17];
    const float* upd_w3 = (const float*)d_in[18];
    const float* upd_b3 = (const float*)d_in[19];
    float* out = (float*)d_out;

    cudaFuncSetAttribute(tc_pair_kernel,
                         cudaFuncAttributeMaxDynamicSharedMemorySize, SMEM_PAIR);

    enc_kernel<<<ROWS/TRE, HD>>>(obs, enc_w1, enc_b1, enc_w2, enc_b2, enc_w3, enc_b3);

    for (int l = 0; l < NLAYERS; l++) {
        const float* w1 = msg_w1 + (size_t)l*(2*HD+1)*MD;
        const float* b1 = msg_b1 + (size_t)l*MD;
        const float* w2 = msg_w2 + (size_t)l*MD*MD;
        const float* b2 = msg_b2 + (size_t)l*MD;
        const float* w3 = msg_w3 + (size_t)l*MD*MD;
        const float* b3 = msg_b3 + (size_t)l*MD;
        const float* uw1 = upd_w1 + (size_t)l*(HD+MD)*HD;
        const float* ub1 = upd_b1 + (size_t)l*HD;
        const float* uw2 = upd_w2 + (size_t)l*HD*HD;
        const float* ub2 = upd_b2 + (size_t)l*HD;
        const float* uw3 = upd_w3 + (size_t)l*HD*HD;
        const float* ub3 = upd_b3 + (size_t)l*HD;

        prep_w2_kernel<<<128, 128>>>(w2);
        pairproj_kernel<<<ROWS/TRU, 256>>>(w1, b1);
        tc_pair_kernel<<<ROWS, 256, SMEM_PAIR>>>(pos, w1 + 2*HD*MD, b2);
        upd_kernel<<<ROWS/TRU, 256>>>(w3, b3, uw1, ub1, uw2, ub2, uw3, ub3,
                                      out, (l == NLAYERS-1) ? 1 : 0);
    }
}

// round 7
// speedup vs baseline: 2.6686x; 1.1249x over previous
#include <cuda_runtime.h>
#include <cuda_bf16.h>
#include <cstdint>
#include <math.h>

#define BB 32
#define NN 128
#define OBSD 32
#define HD 128
#define MD 128
#define NLAYERS 3
#define ROWS (BB*NN)      // 4096
#define TRE 16            // rows/block: encoder
#define TRU 8             // rows/block: pairproj / upd
#define IPB 4             // i-nodes per pair block

// ---------------- scratch (static device globals; no allocation) -----------
__device__ float g_z[ROWS*HD];
__device__ float g_A[ROWS*MD];
__device__ float g_BpT[BB*MD*NN];    // (z @ w1b)^T per batch: [b][f][j]  (fp32)
__device__ float g_S[ROWS*MD];
__device__ __align__(16) __nv_bfloat16 g_Whi[MD*MD];   // w2^T hi  [m][k]
__device__ __align__(16) __nv_bfloat16 g_Wlo[MD*MD];   // w2^T lo  [m][k]

__device__ __forceinline__ uint32_t smem_u32(const void* p) {
    uint32_t a;
    asm("{ .reg .u64 t; cvta.to.shared.u64 t, %1; cvt.u32.u64 %0, t; }" : "=r"(a) : "l"(p));
    return a;
}

// ---------------- encoder: obs(4096x32) -> H -> H -> H --------------------
__global__ void enc_kernel(const float* __restrict__ obs,
                           const float* __restrict__ w1, const float* __restrict__ b1,
                           const float* __restrict__ w2, const float* __restrict__ b2,
                           const float* __restrict__ w3, const float* __restrict__ b3)
{
    __shared__ float s_in[TRE][OBSD];
    __shared__ float s_h[TRE][HD];
    __shared__ float s_h2[TRE][HD];
    const int c = threadIdx.x;
    const int row0 = blockIdx.x * TRE;

    for (int idx = c; idx < TRE*OBSD; idx += HD)
        s_in[idx / OBSD][idx % OBSD] = obs[row0*OBSD + idx];
    __syncthreads();

    float acc[TRE];
#pragma unroll
    for (int r = 0; r < TRE; r++) acc[r] = b1[c];
    for (int k = 0; k < OBSD; k++) {
        float wv = w1[k*HD + c];
#pragma unroll
        for (int r = 0; r < TRE; r++) acc[r] += s_in[r][k]*wv;
    }
#pragma unroll
    for (int r = 0; r < TRE; r++) s_h[r][c] = fmaxf(acc[r], 0.f);
    __syncthreads();

#pragma unroll
    for (int r = 0; r < TRE; r++) acc[r] = b2[c];
    for (int k = 0; k < HD; k++) {
        float wv = w2[k*HD + c];
#pragma unroll
        for (int r = 0; r < TRE; r++) acc[r] += s_h[r][k]*wv;
    }
#pragma unroll
    for (int r = 0; r < TRE; r++) s_h2[r][c] = fmaxf(acc[r], 0.f);
    __syncthreads();

#pragma unroll
    for (int r = 0; r < TRE; r++) acc[r] = b3[c];
    for (int k = 0; k < HD; k++) {
        float wv = w3[k*HD + c];
#pragma unroll
        for (int r = 0; r < TRE; r++) acc[r] += s_h2[r][k]*wv;
    }
#pragma unroll
    for (int r = 0; r < TRE; r++) g_z[(row0+r)*HD + c] = acc[r];
}

// -------- per-node projections, split-k over 2 thread halves --------
__global__ void __launch_bounds__(256) pairproj_kernel(const float* __restrict__ w1,
                                                       const float* __restrict__ b1)
{
    __shared__ float s_z[TRU][HD];
    __shared__ float sPA[TRU][128];
    __shared__ float sPB[TRU][128];
    const int tid = threadIdx.x;
    const int c  = tid & 127;
    const int kh = tid >> 7;
    const int row0 = blockIdx.x * TRU;

    for (int idx = tid; idx < TRU*HD; idx += 256)
        ((float*)s_z)[idx] = g_z[row0*HD + idx];
    __syncthreads();

    float accA[TRU], accB[TRU];
#pragma unroll
    for (int r = 0; r < TRU; r++) { accA[r] = 0.f; accB[r] = 0.f; }
    const int k0 = kh*64;
#pragma unroll 4
    for (int k = k0; k < k0 + 64; k++) {
        float wa = w1[k*MD + c];
        float wb = w1[(HD + k)*MD + c];
#pragma unroll
        for (int r = 0; r < TRU; r++) {
            float zv = s_z[r][k];
            accA[r] += zv*wa;
            accB[r] += zv*wb;
        }
    }
    if (kh == 1) {
#pragma unroll
        for (int r = 0; r < TRU; r++) { sPA[r][c] = accA[r]; sPB[r][c] = accB[r]; }
    }
    __syncthreads();
    if (kh == 0) {
        const int b  = row0 / NN;
        const int j0 = row0 % NN;
        float bias = b1[c];
#pragma unroll
        for (int r = 0; r < TRU; r++) {
            g_A[(row0+r)*MD + c] = accA[r] + sPA[r][c] + bias;
            g_BpT[b*(MD*NN) + c*NN + (j0+r)] = accB[r] + sPB[r][c];
        }
    }
}

// -------- prep: w2 (fp32 [k][m]) -> w2^T hi/lo bf16 [m][k] -----------------
__global__ void prep_w2_kernel(const float* __restrict__ w2)
{
    int e = blockIdx.x * 128 + threadIdx.x;   // 16384 elems
    int m = e >> 7, k = e & 127;
    float v = w2[k*MD + m];
    __nv_bfloat16 hi = __float2bfloat16(v);
    __nv_bfloat16 lo = __float2bfloat16(v - __bfloat162float(hi));
    g_Whi[m*MD + k] = hi;
    g_Wlo[m*MD + k] = lo;
}

// ======================= pair kernel (mma.sync + ldmatrix) ==================
// Block handles IPB=4 i-nodes of one batch b. W hi/lo staged ONCE per block.
// H1 built per-i from fp32 g_BpT (L1-resident after first i) -- R5 numerics.
#define PADH 136                 // halves per row (272 B)
#define ROWB (PADH*2)            // 272
#define TILE_BYTES (128*ROWB)    // 34816
#define OFF_WHI  0
#define OFF_WLO  TILE_BYTES
#define OFF_H1   (2*TILE_BYTES)
#define OFF_AUX  (3*TILE_BYTES)
// aux: sA 4*128f | dsh 4*128f | sW1d 128f | b2s 128f | red 4*128f
#define AUX_SA   0
#define AUX_D    2048
#define AUX_W1D  4096
#define AUX_B2   4608
#define AUX_RED  5120
#define SMEM_PAIR (OFF_AUX + 5120 + 2048)

__device__ __forceinline__ void mma_bf16(float c[4], uint32_t a0, uint32_t a1,
                                         uint32_t a2, uint32_t a3,
                                         uint32_t b0, uint32_t b1) {
    asm volatile(
        "mma.sync.aligned.m16n8k16.row.col.f32.bf16.bf16.f32 "
        "{%0,%1,%2,%3}, {%4,%5,%6,%7}, {%8,%9}, {%0,%1,%2,%3};"
        : "+f"(c[0]), "+f"(c[1]), "+f"(c[2]), "+f"(c[3])
        : "r"(a0), "r"(a1), "r"(a2), "r"(a3), "r"(b0), "r"(b1));
}
#define LDSM_X4(r0, r1, r2, r3, addr) \
    asm volatile("ldmatrix.sync.aligned.m8n8.x4.shared.b16 {%0,%1,%2,%3}, [%4];" \
        : "=r"(r0), "=r"(r1), "=r"(r2), "=r"(r3) : "r"(addr))

__global__ void __launch_bounds__(256, 2) tc_pair_kernel(
    const float* __restrict__ pos,
    const float* __restrict__ w1d,
    const float* __restrict__ b2)
{
    extern __shared__ __align__(16) char s[];
    float* sA   = (float*)(s + OFF_AUX + AUX_SA);
    float* dsh  = (float*)(s + OFF_AUX + AUX_D);
    float* sW1d = (float*)(s + OFF_AUX + AUX_W1D);
    float* b2s  = (float*)(s + OFF_AUX + AUX_B2);
    float* red  = (float*)(s + OFF_AUX + AUX_RED);

    const int tid  = threadIdx.x;
    const int wid  = tid >> 5;
    const int lane = tid & 31;
    const int g    = lane >> 2;
    const int tig  = lane & 3;
    const int wj   = wid & 3;         // j quarter (32 rows)
    const int wm   = wid >> 2;        // m half   (64 cols)
    const int blk  = blockIdx.x;      // 1024 blocks
    const int b    = blk >> 5;
    const int i0   = (blk & 31) * IPB;

    // ---- stage W hi/lo (bf16, padded rows), once per block ----
    {
        float4* dhi = (float4*)(s + OFF_WHI);
        float4* dlo = (float4*)(s + OFF_WLO);
        const float4* shi = (const float4*)g_Whi;
        const float4* slo = (const float4*)g_Wlo;
        for (int i = tid; i < 2048; i += 256) {
            int row = i >> 4, c4 = i & 15;
            dhi[row*17 + c4] = shi[i];
            dlo[row*17 + c4] = slo[i];
        }
    }
    // ---- stage A rows, distances, w1d, bias ----
    for (int t = tid; t < IPB*128; t += 256) {
        int ii = t >> 7, j = t & 127;
        sA[t] = g_A[(size_t)(b*NN + i0 + ii)*MD + j];
        const float2 pi = ((const float2*)pos)[b*NN + i0 + ii];
        const float2 pj = ((const float2*)pos)[b*NN + j];
        float dx = pi.x - pj.x, dy = pi.y - pj.y;
        dsh[t] = sqrtf(dx*dx + dy*dy);
    }
    if (tid < 128) { sW1d[tid] = w1d[tid]; b2s[tid] = b2[tid]; }
    __syncthreads();

    // ---- ldmatrix bases ----
    const uint32_t sbase = smem_u32(s);
    uint32_t aAddr[2];
#pragma unroll
    for (int jt = 0; jt < 2; jt++)
        aAddr[jt] = sbase + OFF_H1 + (uint32_t)(wj*32 + jt*16 + (lane & 15))*ROWB
                  + (uint32_t)(lane >> 4)*16;
    const int bt = lane >> 3;
    const uint32_t brow = (uint32_t)(wm*64 + (bt >> 1)*8 + (lane & 7))*ROWB
                        + (uint32_t)(bt & 1)*16;
    const uint32_t bHi = sbase + OFF_WHI + brow;
    const uint32_t bLo = sbase + OFF_WLO + brow;

    const float* Bp = g_BpT + (size_t)b*(MD*NN);

    for (int ii = 0; ii < IPB; ii++) {
        // ---- build H1[j][k] = relu(A[k] + Bp[k,j] + d[j]*w1d[k]) -> bf16 ----
        // thread: fixed j = tid&127, f-pairs step by 2*(256/128)=... (it strides 256)
        {
            __nv_bfloat162* H1 = (__nv_bfloat162*)(s + OFF_H1);
            const float* dI = dsh + ii*128;
            const float* aI = sA + ii*128;
#pragma unroll
            for (int it = tid; it < 8192; it += 256) {
                int fp = it >> 7, j = it & 127;
                int f0 = fp << 1;
                float d = dI[j];
                float v0 = fmaxf(aI[f0]   + Bp[f0*NN + j]     + d*sW1d[f0],   0.f);
                float v1 = fmaxf(aI[f0+1] + Bp[(f0+1)*NN + j] + d*sW1d[f0+1], 0.f);
                H1[(j*PADH + f0) >> 1] = __floats2bfloat162_rn(v0, v1);
            }
        }
        __syncthreads();

        // ---- MMA: 32j x 64m per warp, K=128, two passes (hi, lo) ----
        float acc[2][8][4];
#pragma unroll
        for (int jt = 0; jt < 2; jt++)
#pragma unroll
            for (int nt = 0; nt < 8; nt++)
#pragma unroll
                for (int q = 0; q < 4; q++) acc[jt][nt][q] = 0.f;

#pragma unroll
        for (int kk = 0; kk < 8; kk++) {
            uint32_t a[2][4];
            LDSM_X4(a[0][0], a[0][1], a[0][2], a[0][3], aAddr[0] + kk*32);
            LDSM_X4(a[1][0], a[1][1], a[1][2], a[1][3], aAddr[1] + kk*32);
#pragma unroll
            for (int pass = 0; pass < 2; pass++) {
                const uint32_t bb = (pass ? bLo : bHi) + kk*32;
#pragma unroll
                for (int p = 0; p < 4; p++) {
                    uint32_t w0, w1r, w2r, w3r;
                    LDSM_X4(w0, w1r, w2r, w3r, bb + p*(16*ROWB));
                    mma_bf16(acc[0][2*p],   a[0][0], a[0][1], a[0][2], a[0][3], w0,  w1r);
                    mma_bf16(acc[1][2*p],   a[1][0], a[1][1], a[1][2], a[1][3], w0,  w1r);
                    mma_bf16(acc[0][2*p+1], a[0][0], a[0][1], a[0][2], a[0][3], w2r, w3r);
                    mma_bf16(acc[1][2*p+1], a[1][0], a[1][1], a[1][2], a[1][3], w2r, w3r);
                }
            }
        }

        // ---- epilogue: +b2, relu, zero diag, reduce over warp's 32 j ----
        const int inode = i0 + ii;
#pragma unroll
        for (int nt = 0; nt < 8; nt++) {
            const int col0 = wm*64 + nt*8 + 2*tig;
            const float bias0 = b2s[col0], bias1 = b2s[col0 + 1];
            float s0 = 0.f, s1 = 0.f;
#pragma unroll
            for (int jt = 0; jt < 2; jt++) {
                int r0 = wj*32 + jt*16 + g;
                int r1 = r0 + 8;
                float v0 = fmaxf(acc[jt][nt][0] + bias0, 0.f);
                float v1 = fmaxf(acc[jt][nt][1] + bias1, 0.f);
                float v2 = fmaxf(acc[jt][nt][2] + bias0, 0.f);
                float v3 = fmaxf(acc[jt][nt][3] + bias1, 0.f);
                if (r0 == inode) { v0 = 0.f; v1 = 0.f; }
                if (r1 == inode) { v2 = 0.f; v3 = 0.f; }
                s0 += v0 + v2;
                s1 += v1 + v3;
            }
#pragma unroll
            for (int off = 4; off < 32; off <<= 1) {
                s0 += __shfl_xor_sync(0xffffffffu, s0, off);
                s1 += __shfl_xor_sync(0xffffffffu, s1, off);
            }
            if (g == 0) {
                red[wj*128 + col0]     = s0;
                red[wj*128 + col0 + 1] = s1;
            }
        }
        __syncthreads();

        if (tid < 128)
            g_S[(size_t)(b*NN + inode)*MD + tid] =
                red[tid] + red[128 + tid] + red[256 + tid] + red[384 + tid];
        // red reads complete before next epilogue writes (guarded by the
        // post-H1-build __syncthreads of the next iteration).
    }
}

// -------- update MLP, split-k over 2 thread halves --------
__global__ void __launch_bounds__(256) upd_kernel(
        const float* __restrict__ w3, const float* __restrict__ b3,
        const float* __restrict__ uw1, const float* __restrict__ ub1,
        const float* __restrict__ uw2, const float* __restrict__ ub2,
        const float* __restrict__ uw3, const float* __restrict__ ub3,
        float* __restrict__ out, int write_out)
{
    __shared__ float sS[TRU][MD];     // S, later reused as u2
    __shared__ float sZ[TRU][HD];
    __shared__ float sMsg[TRU][MD];
    __shared__ float sT[TRU][HD];
    __shared__ float sP[TRU][128];
    const int tid = threadIdx.x;
    const int c  = tid & 127;
    const int kh = tid >> 7;
    const int row0 = blockIdx.x * TRU;

    for (int idx = tid; idx < TRU*MD; idx += 256) {
        ((float*)sS)[idx] = g_S[row0*MD + idx];
        ((float*)sZ)[idx] = g_z[row0*HD + idx];
    }
    __syncthreads();

    float acc[TRU];
#pragma unroll
    for (int r = 0; r < TRU; r++) acc[r] = 0.f;
    {
        const int k0 = kh*64;
#pragma unroll 4
        for (int k = k0; k < k0 + 64; k++) {
            float wv = w3[k*MD + c];
#pragma unroll
            for (int r = 0; r < TRU; r++) acc[r] += sS[r][k]*wv;
        }
    }
    if (kh == 1) { for (int r = 0; r < TRU; r++) sP[r][c] = acc[r]; }
    __syncthreads();
    if (kh == 0) {
        float bias = 127.0f * b3[c];
        for (int r = 0; r < TRU; r++) sMsg[r][c] = acc[r] + sP[r][c] + bias;
    }
    __syncthreads();

#pragma unroll
    for (int r = 0; r < TRU; r++) acc[r] = 0.f;
    if (kh == 0) {
#pragma unroll 4
        for (int k = 0; k < HD; k++) {
            float wv = uw1[k*HD + c];
#pragma unroll
            for (int r = 0; r < TRU; r++) acc[r] += sZ[r][k]*wv;
        }
    } else {
#pragma unroll 4
        for (int k = 0; k < MD; k++) {
            float wv = uw1[(HD + k)*HD + c];
#pragma unroll
            for (int r = 0; r < TRU; r++) acc[r] += sMsg[r][k]*wv;
        }
    }
    if (kh == 1) { for (int r = 0; r < TRU; r++) sP[r][c] = acc[r]; }
    __syncthreads();
    if (kh == 0) {
        float bias = ub1[c];
        for (int r = 0; r < TRU; r++) sT[r][c] = fmaxf(acc[r] + sP[r][c] + bias, 0.f);
    }
    __syncthreads();

#pragma unroll
    for (int r = 0; r < TRU; r++) acc[r] = 0.f;
    {
        const int k0 = kh*64;
#pragma unroll 4
        for (int k = k0; k < k0 + 64; k++) {
            float wv = uw2[k*HD + c];
#pragma unroll
            for (int r = 0; r < TRU; r++) acc[r] += sT[r][k]*wv;
        }
    }
    if (kh == 1) { for (int r = 0; r < TRU; r++) sP[r][c] = acc[r]; }
    __syncthreads();
    if (kh == 0) {
        float bias = ub2[c];
        for (int r = 0; r < TRU; r++) sS[r][c] = fmaxf(acc[r] + sP[r][c] + bias, 0.f);
    }
    __syncthreads();

#pragma unroll
    for (int r = 0; r < TRU; r++) acc[r] = 0.f;
    {
        const int k0 = kh*64;
#pragma unroll 4
        for (int k = k0; k < k0 + 64; k++) {
            float wv = uw3[k*HD + c];
#pragma unroll
            for (int r = 0; r < TRU; r++) acc[r] += sS[r][k]*wv;
        }
    }
    if (kh == 1) { for (int r = 0; r < TRU; r++) sP[r][c] = acc[r]; }
    __syncthreads();
    if (kh == 0) {
        float bias = ub3[c];
        if (write_out) {
            for (int r = 0; r < TRU; r++) out[(row0+r)*HD + c] = acc[r] + sP[r][c] + bias;
        } else {
            for (int r = 0; r < TRU; r++) g_z[(row0+r)*HD + c] = acc[r] + sP[r][c] + bias;
        }
    }
}

extern "C" void kernel_launch(void* const* d_in, const int* in_sizes, int n_in,
                              void* d_out, int out_size)
{
    const float* obs    = (const float*)d_in[0];
    const float* pos    = (const float*)d_in[1];
    const float* enc_w1 = (const float*)d_in[2];
    const float* enc_b1 = (const float*)d_in[3];
    const float* enc_w2 = (const float*)d_in[4];
    const float* enc_b2 = (const float*)d_in[5];
    const float* enc_w3 = (const float*)d_in[6];
    const float* enc_b3 = (const float*)d_in[7];
    const float* msg_w1 = (const float*)d_in[8];
    const float* msg_b1 = (const float*)d_in[9];
    const float* msg_w2 = (const float*)d_in[10];
    const float* msg_b2 = (const float*)d_in[11];
    const float* msg_w3 = (const float*)d_in[12];
    const float* msg_b3 = (const float*)d_in[13];
    const float* upd_w1 = (const float*)d_in[14];
    const float* upd_b1 = (const float*)d_in[15];
    const float* upd_w2 = (const float*)d_in[16];
    const float* upd_b2 = (const float*)d_in[17];
    const float* upd_w3 = (const float*)d_in[18];
    const float* upd_b3 = (const float*)d_in[19];
    float* out = (float*)d_out;

    cudaFuncSetAttribute(tc_pair_kernel,
                         cudaFuncAttributeMaxDynamicSharedMemorySize, SMEM_PAIR);

    enc_kernel<<<ROWS/TRE, HD>>>(obs, enc_w1, enc_b1, enc_w2, enc_b2, enc_w3, enc_b3);

    for (int l = 0; l < NLAYERS; l++) {
        const float* w1 = msg_w1 + (size_t)l*(2*HD+1)*MD;
        const float* b1 = msg_b1 + (size_t)l*MD;
        const float* w2 = msg_w2 + (size_t)l*MD*MD;
        const float* b2 = msg_b2 + (size_t)l*MD;
        const float* w3 = msg_w3 + (size_t)l*MD*MD;
        const float* b3 = msg_b3 + (size_t)l*MD;
        const float* uw1 = upd_w1 + (size_t)l*(HD+MD)*HD;
        const float* ub1 = upd_b1 + (size_t)l*HD;
        const float* uw2 = upd_w2 + (size_t)l*HD*HD;
        const float* ub2 = upd_b2 + (size_t)l*HD;
        const float* uw3 = upd_w3 + (size_t)l*HD*HD;
        const float* ub3 = upd_b3 + (size_t)l*HD;

        prep_w2_kernel<<<128, 128>>>(w2);
        pairproj_kernel<<<ROWS/TRU, 256>>>(w1, b1);
        tc_pair_kernel<<<ROWS/IPB, 256, SMEM_PAIR>>>(pos, w1 + 2*HD*MD, b2);
        upd_kernel<<<ROWS/TRU, 256>>>(w3, b3, uw1, ub1, uw2, ub2, uw3, ub3,
                                      out, (l == NLAYERS-1) ? 1 : 0);
    }
}